// round 8
// baseline (speedup 1.0000x reference)
#include <cuda_runtime.h>
#include <cuda_bf16.h>
#include <math.h>
#include <stdint.h>

#define T_ 512
#define B_ 64
#define I_ 1024
#define H_ 1024
#define L_ 2
#define BH (B_*H_)
#define NCTAS 128

// ---------------- static device scratch ----------------
__device__ float g_gx[(size_t)3*L_*T_*B_*H_];
__device__ __nv_bfloat16 g_Whi[(size_t)3*L_*H_*I_], g_Wlo[(size_t)3*L_*H_*I_];
__device__ __nv_bfloat16 g_Uhi[(size_t)3*L_*H_*H_], g_Ulo[(size_t)3*L_*H_*H_];
__device__ __nv_bfloat16 g_xhi[(size_t)T_*B_*I_], g_xlo[(size_t)T_*B_*I_];
__device__ float g_h[2][L_*BH];
__device__ __nv_bfloat16 g_hhi[2][L_*BH], g_hlo[2][L_*BH];
__device__ float g_z[L_*BH];
__device__ __nv_bfloat16 g_rhhi[L_*BH], g_rhlo[L_*BH];
__device__ unsigned g_cnt;      // cumulative grid-barrier counter (reset each launch)

// ---------------- helpers ----------------
__device__ __forceinline__ void cpa8(void* sdst, const void* gsrc){
    uint32_t s = (uint32_t)__cvta_generic_to_shared(sdst);
    asm volatile("cp.async.ca.shared.global [%0], [%1], 8;\n" :: "r"(s), "l"(gsrc));
}
__device__ __forceinline__ void cpa_commit(){ asm volatile("cp.async.commit_group;\n" ::); }
__device__ __forceinline__ void cpa_wait0(){ asm volatile("cp.async.wait_group 0;\n" ::); }
__device__ __forceinline__ void cpa_wait1(){ asm volatile("cp.async.wait_group 1;\n" ::); }
__device__ __forceinline__ void cpa_wait2(){ asm volatile("cp.async.wait_group 2;\n" ::); }

__device__ __forceinline__ void mma_bf16(float c[4], const uint32_t a[4], const uint32_t b[2]){
    asm volatile("mma.sync.aligned.m16n8k16.row.col.f32.bf16.bf16.f32 "
        "{%0,%1,%2,%3},{%4,%5,%6,%7},{%8,%9},{%0,%1,%2,%3};\n"
        : "+f"(c[0]), "+f"(c[1]), "+f"(c[2]), "+f"(c[3])
        : "r"(a[0]), "r"(a[1]), "r"(a[2]), "r"(a[3]), "r"(b[0]), "r"(b[1]));
}

// Device-wide barrier: cumulative counter, release-arrive + acquire-spin.
__device__ __forceinline__ void grid_sync(unsigned target){
    __syncthreads();
    if (threadIdx.x == 0){
        asm volatile("red.release.gpu.global.add.u32 [%0], 1;\n" :: "l"(&g_cnt) : "memory");
        unsigned v;
        do {
            asm volatile("ld.acquire.gpu.global.u32 %0, [%1];\n" : "=r"(v) : "l"(&g_cnt) : "memory");
        } while (v < target);
    }
    __syncthreads();
}

// SMEM tiles: rows padded to 40 halves (80B) -> conflict-free fragment LDS
template<int BN, int NS>
struct SmemT {
    __nv_bfloat16 A[NS][2][64*40];
    __nv_bfloat16 B[NS][2][BN*40];
};

template<int BN, int NS>
__device__ __forceinline__ void load_stage(SmemT<BN,NS>* sm, int st,
        const __nv_bfloat16* Ahi, const __nv_bfloat16* Alo,
        const __nv_bfloat16* Bhi, const __nv_bfloat16* Blo, int k0, int tid){
    #pragma unroll
    for (int c = 0; c < 4; ++c){
        int cc = tid + c*128;
        int row = cc >> 3, ck = cc & 7;
        int so = row*40 + ck*4;
        int go = row*1024 + k0 + ck*4;
        cpa8(&sm->A[st][0][so], Ahi + go);
        cpa8(&sm->A[st][1][so], Alo + go);
    }
    #pragma unroll
    for (int c = 0; c < BN/16; ++c){
        int cc = tid + c*128;
        int row = cc >> 3, ck = cc & 7;
        int so = row*40 + ck*4;
        int go = row*1024 + k0 + ck*4;
        cpa8(&sm->B[st][0][so], Bhi + go);
        cpa8(&sm->B[st][1][so], Blo + go);
    }
}

// C[64 x BN] = A[64 x 1024] * B[BN x 1024]^T, bf16x3 (AhBh + AhBl + AlBh), fp32 acc.
// 128 threads = 4 warps in 2x2, warp tile 32 x (BN/2).
template<int BN, int NS>
__device__ __forceinline__ void gemm_core(SmemT<BN,NS>* sm,
        const __nv_bfloat16* Ahi, const __nv_bfloat16* Alo,
        const __nv_bfloat16* Bhi, const __nv_bfloat16* Blo,
        float acc[2][BN/16][4])
{
    constexpr int NF = BN/16;
    const int tid = threadIdx.x;
    const int lane = tid & 31, wid = tid >> 5;
    const int wm = wid >> 1, wn = wid & 1;
    const int gq = lane >> 2, q = lane & 3;

    #pragma unroll
    for (int s = 0; s < NS-1; ++s){
        load_stage<BN,NS>(sm, s, Ahi, Alo, Bhi, Blo, s*32, tid);
        cpa_commit();
    }

    int st = 0, pf = NS-1;
    #pragma unroll 1
    for (int kt = 0; kt < 32; ++kt){
        if (kt + NS - 1 < 32){
            load_stage<BN,NS>(sm, pf, Ahi, Alo, Bhi, Blo, (kt+NS-1)*32, tid);
            cpa_commit();
            pf = (pf == NS-1) ? 0 : pf+1;
        }
        // groups allowed outstanding so that stage `st` is complete:
        int ahead = ((kt + NS < 32) ? (kt + NS) : 32) - (kt + 1);
        if (ahead <= 0) cpa_wait0();
        else if (ahead == 1) cpa_wait1();
        else cpa_wait2();
        __syncthreads();
        #pragma unroll
        for (int k16 = 0; k16 < 2; ++k16){
            uint32_t ah[2][4], al[2][4];
            #pragma unroll
            for (int mf = 0; mf < 2; ++mf){
                int ao = (wm*32 + mf*16 + gq)*40 + k16*16 + q*2;
                const __nv_bfloat16* ph = &sm->A[st][0][ao];
                const __nv_bfloat16* pl = &sm->A[st][1][ao];
                ah[mf][0] = *(const uint32_t*)(ph);
                ah[mf][1] = *(const uint32_t*)(ph + 320);
                ah[mf][2] = *(const uint32_t*)(ph + 8);
                ah[mf][3] = *(const uint32_t*)(ph + 328);
                al[mf][0] = *(const uint32_t*)(pl);
                al[mf][1] = *(const uint32_t*)(pl + 320);
                al[mf][2] = *(const uint32_t*)(pl + 8);
                al[mf][3] = *(const uint32_t*)(pl + 328);
            }
            #pragma unroll
            for (int nf = 0; nf < NF; ++nf){
                int bo = (wn*(BN/2) + nf*8 + gq)*40 + k16*16 + q*2;
                const __nv_bfloat16* pb = &sm->B[st][0][bo];
                const __nv_bfloat16* qb = &sm->B[st][1][bo];
                uint32_t bh2[2], bl2[2];
                bh2[0] = *(const uint32_t*)(pb);
                bh2[1] = *(const uint32_t*)(pb + 8);
                bl2[0] = *(const uint32_t*)(qb);
                bl2[1] = *(const uint32_t*)(qb + 8);
                #pragma unroll
                for (int mf = 0; mf < 2; ++mf){
                    mma_bf16(acc[mf][nf], ah[mf], bh2);
                    mma_bf16(acc[mf][nf], ah[mf], bl2);
                    mma_bf16(acc[mf][nf], al[mf], bh2);
                }
            }
        }
        __syncthreads();
        st = (st == NS-1) ? 0 : st+1;
    }
}

// ---------------- prep kernels ----------------
__global__ void k_split_sel(const float* __restrict__ src, int sel, size_t off, size_t n){
    __nv_bfloat16 *hi, *lo;
    if (sel == 0){ hi = g_Whi; lo = g_Wlo; }
    else if (sel == 1){ hi = g_Uhi; lo = g_Ulo; }
    else { hi = g_xhi; lo = g_xlo; }
    size_t i = (size_t)blockIdx.x*blockDim.x + threadIdx.x;
    size_t stp = (size_t)gridDim.x*blockDim.x;
    for (; i < n; i += stp){
        float v = src[i];
        __nv_bfloat16 h = __float2bfloat16(v);
        hi[off+i] = h;
        lo[off+i] = __float2bfloat16(v - __bfloat162float(h));
    }
}

__global__ void k_init_h(const float* __restrict__ h0){
    int i = blockIdx.x*blockDim.x + threadIdx.x;
    if (i == 0) g_cnt = 0;               // reset grid barrier each launch (replay-safe)
    if (i < L_*BH){
        float v = h0[i];
        g_h[0][i] = v;
        __nv_bfloat16 h = __float2bfloat16(v);
        g_hhi[0][i] = h;
        g_hlo[0][i] = __float2bfloat16(v - __bfloat162float(h));
    }
}

// ---------------- input projection GEMM: g_gx = x*W^T + b ----------------
// grid (T, 16, 6): t, n-tile(64), gl = gate*2 + l.  Tile M=64(batch), N=64, K=1024.
__global__ void __launch_bounds__(128) k_gemm_input(const float* __restrict__ bz,
        const float* __restrict__ br, const float* __restrict__ bhb){
    constexpr int BN = 64;
    const int t = blockIdx.x, ny = blockIdx.y, gl = blockIdx.z;
    const __nv_bfloat16* Ahi = g_xhi + (size_t)t*B_*I_;
    const __nv_bfloat16* Alo = g_xlo + (size_t)t*B_*I_;
    const size_t boff = ((size_t)gl*H_ + (size_t)ny*BN)*I_;
    __shared__ SmemT<BN,2> sm;
    float acc[2][BN/16][4] = {};
    gemm_core<BN,2>(&sm, Ahi, Alo, g_Whi + boff, g_Wlo + boff, acc);

    const int gate = gl >> 1, l = gl & 1;
    const float* bias = (gate == 0) ? bz : ((gate == 1) ? br : bhb);
    float* dst = g_gx + ((size_t)gl*T_ + t)*BH;
    const int lane = threadIdx.x & 31, wid = threadIdx.x >> 5;
    const int wm = wid >> 1, wn = wid & 1, gq = lane >> 2, q = lane & 3;
    #pragma unroll
    for (int mf = 0; mf < 2; ++mf)
    #pragma unroll
    for (int nf = 0; nf < BN/16; ++nf)
    #pragma unroll
    for (int e = 0; e < 4; ++e){
        int row = wm*32 + mf*16 + gq + ((e>>1)<<3);
        int col = ny*BN + wn*(BN/2) + nf*8 + q*2 + (e&1);
        dst[(size_t)row*H_ + col] = acc[mf][nf][e] + bias[l*H_ + col];
    }
}

// ---------------- persistent recurrence kernel ----------------
// grid = 128 CTAs x 128 threads, all co-resident (<= 148 SMs, 46KB smem each).
// Per step: phase A (z,r for both layers; 128 tile-jobs of 64x32), grid barrier,
// phase B (hh + state update; 64 tile-jobs on CTAs 0..63), grid barrier.
__global__ void __launch_bounds__(128, 1) k_recur(float* __restrict__ out){
    constexpr int BN = 32;
    __shared__ SmemT<BN,3> sm;
    const int c = blockIdx.x;
    const int tid = threadIdx.x;
    const int lane = tid & 31, wid = tid >> 5;
    const int wm = wid >> 1, wn = wid & 1, gq = lane >> 2, q = lane & 3;
    unsigned target = 0;

    for (int t = 0; t < T_; ++t){
        const int cur = t & 1, nxt = cur ^ 1;

        // ---- phase A: z (gate 0) and r (gate 1) ----
        {
            const int gate = c >> 6, l = (c >> 5) & 1, ny = c & 31;
            const __nv_bfloat16* Ahi = g_hhi[cur] + l*BH;
            const __nv_bfloat16* Alo = g_hlo[cur] + l*BH;
            const size_t boff = ((size_t)(gate*L_ + l)*H_ + (size_t)ny*BN)*H_;
            float acc[2][BN/16][4] = {};
            gemm_core<BN,3>(&sm, Ahi, Alo, g_Uhi + boff, g_Ulo + boff, acc);

            const float* gx = g_gx + ((size_t)(gate*L_ + l)*T_ + t)*BH;
            #pragma unroll
            for (int mf = 0; mf < 2; ++mf)
            #pragma unroll
            for (int nf = 0; nf < BN/16; ++nf)
            #pragma unroll
            for (int e = 0; e < 4; ++e){
                int row = wm*32 + mf*16 + gq + ((e>>1)<<3);
                int col = ny*BN + wn*(BN/2) + nf*8 + q*2 + (e&1);
                int idx = l*BH + row*H_ + col;
                float pre = acc[mf][nf][e] + gx[row*H_ + col];
                float sg = 1.0f/(1.0f + expf(-pre));
                if (gate == 0){
                    g_z[idx] = sg;
                } else {
                    float rh = sg * g_h[cur][idx];
                    __nv_bfloat16 h = __float2bfloat16(rh);
                    g_rhhi[idx] = h;
                    g_rhlo[idx] = __float2bfloat16(rh - __bfloat162float(h));
                }
            }
        }
        target += NCTAS; grid_sync(target);

        // ---- phase B: hh + GRU update ----
        if (c < 64){
            const int l = c >> 5, ny = c & 31;
            const __nv_bfloat16* Ahi = g_rhhi + l*BH;
            const __nv_bfloat16* Alo = g_rhlo + l*BH;
            const size_t boff = ((size_t)(2*L_ + l)*H_ + (size_t)ny*BN)*H_;
            float acc[2][BN/16][4] = {};
            gemm_core<BN,3>(&sm, Ahi, Alo, g_Uhi + boff, g_Ulo + boff, acc);

            const float* gx = g_gx + ((size_t)(2*L_ + l)*T_ + t)*BH;
            #pragma unroll
            for (int mf = 0; mf < 2; ++mf)
            #pragma unroll
            for (int nf = 0; nf < BN/16; ++nf)
            #pragma unroll
            for (int e = 0; e < 4; ++e){
                int row = wm*32 + mf*16 + gq + ((e>>1)<<3);
                int col = ny*BN + wn*(BN/2) + nf*8 + q*2 + (e&1);
                int idx = l*BH + row*H_ + col;
                float hh = tanhf(acc[mf][nf][e] + gx[row*H_ + col]);
                float z  = g_z[idx];
                float ho = g_h[cur][idx];
                float hn = ho + z*(hh - ho);
                g_h[nxt][idx] = hn;
                __nv_bfloat16 h = __float2bfloat16(hn);
                g_hhi[nxt][idx] = h;
                g_hlo[nxt][idx] = __float2bfloat16(hn - __bfloat162float(h));
                if (l == 1) out[((size_t)t*B_ + row)*H_ + col] = hn;
            }
        }
        target += NCTAS; grid_sync(target);
    }
}

__global__ void k_final(float* __restrict__ dst){
    int i = blockIdx.x*blockDim.x + threadIdx.x;
    if (i < L_*BH) dst[i] = g_h[0][i];   // after 512 steps (even), state is in buffer 0
}

// ---------------- launch ----------------
extern "C" void kernel_launch(void* const* d_in, const int* in_sizes, int n_in,
                              void* d_out, int out_size){
    cudaStream_t s = cudaStreamPerThread;
    const float* x  = (const float*)d_in[0];
    const float* h0 = (const float*)d_in[1];
    const float* Wz = (const float*)d_in[2];
    const float* Uz = (const float*)d_in[3];
    const float* bz = (const float*)d_in[4];
    const float* Wr = (const float*)d_in[5];
    const float* Ur = (const float*)d_in[6];
    const float* br = (const float*)d_in[7];
    const float* Wh = (const float*)d_in[8];
    const float* Uh = (const float*)d_in[9];
    const float* bh = (const float*)d_in[10];
    float* out = (float*)d_out;

    const size_t nW = (size_t)L_*H_*I_;
    k_split_sel<<<1024, 256, 0, s>>>(Wz, 0, 0,    nW);
    k_split_sel<<<1024, 256, 0, s>>>(Wr, 0, nW,   nW);
    k_split_sel<<<1024, 256, 0, s>>>(Wh, 0, 2*nW, nW);
    k_split_sel<<<1024, 256, 0, s>>>(Uz, 1, 0,    nW);
    k_split_sel<<<1024, 256, 0, s>>>(Ur, 1, nW,   nW);
    k_split_sel<<<1024, 256, 0, s>>>(Uh, 1, 2*nW, nW);
    k_split_sel<<<2048, 256, 0, s>>>(x,  2, 0, (size_t)T_*B_*I_);
    k_init_h<<<(L_*BH + 255)/256, 256, 0, s>>>(h0);

    // input projections for all t, layers, gates (parallel, tensor-core)
    k_gemm_input<<<dim3(T_, H_/64, 3*L_), 128, 0, s>>>(bz, br, bh);

    // whole recurrence in ONE persistent kernel (2 grid barriers per step)
    k_recur<<<NCTAS, 128, 0, s>>>(out);

    k_final<<<(L_*BH + 255)/256, 256, 0, s>>>(out + (size_t)T_*B_*H_);
}